// round 4
// baseline (speedup 1.0000x reference)
#include <cuda_runtime.h>
#include <cuda_fp16.h>

// Problem constants
#define Bc   1024
#define Tc   512
#define EMBc 100
#define H1c  128
#define G1c  512   // 4*H1
#define H2c  64
#define G2c  256   // 4*H2
#define Mtot (Bc*Tc)  // 524288

// Scratch (static device allocations; ~1.75 GiB)
__device__ float g_xw1[(size_t)Bc * Tc * G1c];  // [b][t][512]  1 GiB
__device__ float g_hs1[(size_t)Bc * Tc * H1c];  // [b][t][128]  256 MiB
__device__ float g_xw2[(size_t)Bc * Tc * G2c];  // [b][t][256]  512 MiB

__device__ __forceinline__ float sigf(float x) { return 1.f / (1.f + __expf(-x)); }

// ---------------------------------------------------------------------------
// GEMM: out[m][n] = sum_k A[m][k]*W[n][k] + ba[n] + bb[n]
// M = 524288 (fixed). BM=128, BN=128, BK=8, 256 threads, 8x8 microtile.
// ---------------------------------------------------------------------------
template <int N, int K>
__global__ void __launch_bounds__(256, 2) gemm_bias(const float* __restrict__ A,
                                                    const float* __restrict__ W,
                                                    const float* __restrict__ ba,
                                                    const float* __restrict__ bb,
                                                    float* __restrict__ out)
{
    constexpr int BM = 128, BN = 128, BK = 8;
    __shared__ float As[BK][BM + 4];
    __shared__ float Ws[BK][BN + 4];

    const int tid = threadIdx.x;
    const int bm  = blockIdx.y * BM;
    const int bn  = blockIdx.x * BN;
    const int tm  = (tid >> 4) * 8;
    const int tn  = (tid & 15) * 8;

    float acc[8][8];
#pragma unroll
    for (int i = 0; i < 8; i++)
#pragma unroll
        for (int j = 0; j < 8; j++) acc[i][j] = 0.f;

    for (int kt = 0; kt < K; kt += BK) {
#pragma unroll
        for (int i = 0; i < 4; i++) {
            int idx = tid + i * 256;          // 0..1023
            int m = idx >> 3, k = idx & 7;
            As[k][m] = (kt + k < K) ? A[(size_t)(bm + m) * K + kt + k] : 0.f;
        }
#pragma unroll
        for (int i = 0; i < 4; i++) {
            int idx = tid + i * 256;
            int n = idx >> 3, k = idx & 7;
            Ws[k][n] = (kt + k < K) ? W[(size_t)(bn + n) * K + kt + k] : 0.f;
        }
        __syncthreads();
#pragma unroll
        for (int k = 0; k < BK; k++) {
            float a[8], w[8];
#pragma unroll
            for (int i = 0; i < 8; i++) a[i] = As[k][tm + i];
#pragma unroll
            for (int i = 0; i < 8; i++) w[i] = Ws[k][tn + i];
#pragma unroll
            for (int i = 0; i < 8; i++)
#pragma unroll
                for (int j = 0; j < 8; j++) acc[i][j] = fmaf(a[i], w[j], acc[i][j]);
        }
        __syncthreads();
    }

#pragma unroll
    for (int i = 0; i < 8; i++) {
        size_t m = (size_t)bm + tm + i;
#pragma unroll
        for (int j = 0; j < 8; j++) {
            int n = bn + tn + j;
            out[m * N + n] = acc[i][j] + ba[n] + bb[n];
        }
    }
}

// ---------------------------------------------------------------------------
// LSTM layer 1 recurrence. Batch-parallel persistent blocks.
// 128 blocks x 512 threads, 8 batch rows per block. W_hh fp16 in smem.
// smem: half Wsh[512][130] (133120 B) + float hsh[8][128] (4096 B)
// ---------------------------------------------------------------------------
#define SMEM1 (512 * 130 * 2 + 8 * 128 * 4)

__global__ void __launch_bounds__(512) lstm1_kernel(const float* __restrict__ xw,   // [B][T][512]
                                                    const float* __restrict__ Whh,  // [512][128]
                                                    float* __restrict__ hs1)        // [B][T][128]
{
    extern __shared__ char smraw[];
    __half* Wsh = (__half*)smraw;                    // [512][130]
    float*  hsh = (float*)(smraw + 512 * 130 * 2);   // [8][128]

    const int tid = threadIdx.x;
    const int b0  = blockIdx.x * 8;

    for (int i = tid; i < 512 * 128; i += 512) {
        int g = i >> 7, k = i & 127;
        Wsh[g * 130 + k] = __float2half(Whh[i]);
    }
    for (int i = tid; i < 8 * 128; i += 512) hsh[i] = 0.f;
    __syncthreads();

    const int j  = tid & 127;   // hidden unit
    const int bh = tid >> 7;    // 0..3 -> batch rows bh*2 + {0,1}

    const __half* wi = Wsh + (size_t)(j)*130;
    const __half* wf = Wsh + (size_t)(128 + j) * 130;
    const __half* wg = Wsh + (size_t)(256 + j) * 130;
    const __half* wo = Wsh + (size_t)(384 + j) * 130;

    float c[2] = {0.f, 0.f};

    for (int t = 0; t < Tc; t++) {
        float ai[2] = {0.f, 0.f}, af[2] = {0.f, 0.f};
        float ag[2] = {0.f, 0.f}, ao[2] = {0.f, 0.f};

#pragma unroll 16
        for (int k = 0; k < 128; k += 2) {
            float2 vi = __half22float2(*(const __half2*)(wi + k));
            float2 vf = __half22float2(*(const __half2*)(wf + k));
            float2 vg = __half22float2(*(const __half2*)(wg + k));
            float2 vo = __half22float2(*(const __half2*)(wo + k));
#pragma unroll
            for (int b = 0; b < 2; b++) {
                float2 h2 = *(const float2*)(hsh + (bh * 2 + b) * 128 + k);
                ai[b] = fmaf(vi.x, h2.x, fmaf(vi.y, h2.y, ai[b]));
                af[b] = fmaf(vf.x, h2.x, fmaf(vf.y, h2.y, af[b]));
                ag[b] = fmaf(vg.x, h2.x, fmaf(vg.y, h2.y, ag[b]));
                ao[b] = fmaf(vo.x, h2.x, fmaf(vo.y, h2.y, ao[b]));
            }
        }

        float hv[2];
#pragma unroll
        for (int b = 0; b < 2; b++) {
            int bb = b0 + bh * 2 + b;
            const float* xr = xw + ((size_t)bb * Tc + t) * 512;
            float zi = ai[b] + xr[j];
            float zf = af[b] + xr[128 + j];
            float zg = ag[b] + xr[256 + j];
            float zo = ao[b] + xr[384 + j];
            float ig = sigf(zi), fg = sigf(zf), og = sigf(zo);
            float gg = tanhf(zg);
            c[b]  = fg * c[b] + ig * gg;
            hv[b] = og * tanhf(c[b]);
        }

        __syncthreads();  // all reads of old h done
#pragma unroll
        for (int b = 0; b < 2; b++) {
            int rb = bh * 2 + b;
            hsh[rb * 128 + j] = hv[b];
            hs1[((size_t)(b0 + rb) * Tc + t) * 128 + j] = hv[b];
        }
        __syncthreads();
    }
}

// ---------------------------------------------------------------------------
// LSTM layer 2 recurrence + fused FC head.
// 128 blocks x 512 threads, 8 batch rows per block. W_hh fp32 in smem.
// smem: float Wsh[256][66] (67584 B) + float hsh[8][64] (2048 B)
// ---------------------------------------------------------------------------
#define SMEM2 (256 * 66 * 4 + 8 * 64 * 4)

__global__ void __launch_bounds__(512) lstm2_kernel(const float* __restrict__ xw,   // [B][T][256]
                                                    const float* __restrict__ Whh,  // [256][64]
                                                    const float* __restrict__ fc1w,
                                                    const float* __restrict__ fc1b,
                                                    const float* __restrict__ fc2w,
                                                    const float* __restrict__ fc2b,
                                                    float* __restrict__ out)
{
    extern __shared__ float sm[];
    float* Wsh = sm;               // [256][66]
    float* hsh = sm + 256 * 66;    // [8][64]

    const int tid = threadIdx.x;
    const int b0  = blockIdx.x * 8;

    for (int i = tid; i < 256 * 64; i += 512) {
        int g = i >> 6, k = i & 63;
        Wsh[g * 66 + k] = Whh[i];
    }
    for (int i = tid; i < 8 * 64; i += 512) hsh[i] = 0.f;
    __syncthreads();

    const int j  = tid & 63;    // hidden unit
    const int bh = tid >> 6;    // 0..7 -> one batch row each

    const float* wi = Wsh + (size_t)(j)*66;
    const float* wf = Wsh + (size_t)(64 + j) * 66;
    const float* wg = Wsh + (size_t)(128 + j) * 66;
    const float* wo = Wsh + (size_t)(192 + j) * 66;

    float c = 0.f;

    for (int t = 0; t < Tc; t++) {
        float ai = 0.f, af = 0.f, ag = 0.f, ao = 0.f;
#pragma unroll 16
        for (int k = 0; k < 64; k += 2) {
            float2 vi = *(const float2*)(wi + k);
            float2 vf = *(const float2*)(wf + k);
            float2 vg = *(const float2*)(wg + k);
            float2 vo = *(const float2*)(wo + k);
            float2 h2 = *(const float2*)(hsh + bh * 64 + k);
            ai = fmaf(vi.x, h2.x, fmaf(vi.y, h2.y, ai));
            af = fmaf(vf.x, h2.x, fmaf(vf.y, h2.y, af));
            ag = fmaf(vg.x, h2.x, fmaf(vg.y, h2.y, ag));
            ao = fmaf(vo.x, h2.x, fmaf(vo.y, h2.y, ao));
        }

        int bb = b0 + bh;
        const float* xr = xw + ((size_t)bb * Tc + t) * 256;
        float zi = ai + xr[j];
        float zf = af + xr[64 + j];
        float zg = ag + xr[128 + j];
        float zo = ao + xr[192 + j];
        float ig = sigf(zi), fg = sigf(zf), og = sigf(zo);
        float gg = tanhf(zg);
        c = fg * c + ig * gg;
        float hv = og * tanhf(c);

        __syncthreads();
        hsh[bh * 64 + j] = hv;
        __syncthreads();
    }

    // FC head: warp w handles batch row w (warps 0..7 of 16)
    const int warp = tid >> 5, lane = tid & 31;
    if (warp < 8) {
        float acc = fc1b[lane];
#pragma unroll
        for (int k = 0; k < 64; k++)
            acc = fmaf(hsh[warp * 64 + k], fc1w[lane * 64 + k], acc);
        acc = fmaxf(acc, 0.f);
        float v = acc * fc2w[lane];
#pragma unroll
        for (int off = 16; off; off >>= 1) v += __shfl_down_sync(0xffffffffu, v, off);
        if (lane == 0) out[b0 + warp] = sigf(v + fc2b[0]);
    }
}

// ---------------------------------------------------------------------------
extern "C" void kernel_launch(void* const* d_in, const int* in_sizes, int n_in,
                              void* d_out, int out_size)
{
    (void)in_sizes; (void)n_in; (void)out_size;
    const float* X     = (const float*)d_in[0];
    const float* W1_ih = (const float*)d_in[1];
    const float* W1_hh = (const float*)d_in[2];
    const float* b1_ih = (const float*)d_in[3];
    const float* b1_hh = (const float*)d_in[4];
    const float* W2_ih = (const float*)d_in[5];
    const float* W2_hh = (const float*)d_in[6];
    const float* b2_ih = (const float*)d_in[7];
    const float* b2_hh = (const float*)d_in[8];
    const float* fc1w  = (const float*)d_in[9];
    const float* fc1b  = (const float*)d_in[10];
    const float* fc2w  = (const float*)d_in[11];
    const float* fc2b  = (const float*)d_in[12];
    float* out = (float*)d_out;

    float *xw1, *hs1, *xw2;
    cudaGetSymbolAddress((void**)&xw1, g_xw1);
    cudaGetSymbolAddress((void**)&hs1, g_hs1);
    cudaGetSymbolAddress((void**)&xw2, g_xw2);

    static int attr_done = 0;
    if (!attr_done) {
        cudaFuncSetAttribute(lstm1_kernel, cudaFuncAttributeMaxDynamicSharedMemorySize, SMEM1);
        cudaFuncSetAttribute(lstm2_kernel, cudaFuncAttributeMaxDynamicSharedMemorySize, SMEM2);
        attr_done = 1;
    }

    // 1) xw1[b][t][g] = X @ W1_ih^T + (b1_ih + b1_hh)
    gemm_bias<G1c, EMBc><<<dim3(G1c / 128, Mtot / 128), 256>>>(X, W1_ih, b1_ih, b1_hh, xw1);
    // 2) layer-1 recurrence -> hs1
    lstm1_kernel<<<Bc / 8, 512, SMEM1>>>(xw1, W1_hh, hs1);
    // 3) xw2[b][t][g] = hs1 @ W2_ih^T + (b2_ih + b2_hh)
    gemm_bias<G2c, H1c><<<dim3(G2c / 128, Mtot / 128), 256>>>(hs1, W2_ih, b2_ih, b2_hh, xw2);
    // 4) layer-2 recurrence + FC head -> out
    lstm2_kernel<<<Bc / 8, 512, SMEM2>>>(xw2, W2_hh, fc1w, fc1b, fc2w, fc2b, out);
}

// round 5
// speedup vs baseline: 4.9078x; 4.9078x over previous
#include <cuda_runtime.h>
#include <cuda_fp16.h>
#include <cstdint>

// Problem constants
#define Bc   1024
#define Tc   512
#define EMBc 100
#define H1c  128
#define G1c  512   // 4*H1
#define H2c  64
#define G2c  256   // 4*H2
#define Mtot (Bc*Tc)  // 524288

// Scratch
__device__ float g_xw1[(size_t)Mtot * G1c];  // [b][t][512]
__device__ float g_hs1[(size_t)Mtot * H1c];  // [b][t][128]
__device__ float g_xw2[(size_t)Mtot * G2c];  // [b][t][256]

// ---------------------------------------------------------------------------
// helpers
// ---------------------------------------------------------------------------
__device__ __forceinline__ uint32_t s2u(const void* p) {
    return (uint32_t)__cvta_generic_to_shared(p);
}
__device__ __forceinline__ void ldm_x4(uint32_t& a0, uint32_t& a1, uint32_t& a2, uint32_t& a3,
                                       uint32_t addr) {
    asm volatile("ldmatrix.sync.aligned.m8n8.x4.shared.b16 {%0,%1,%2,%3}, [%4];"
                 : "=r"(a0), "=r"(a1), "=r"(a2), "=r"(a3) : "r"(addr));
}
__device__ __forceinline__ void ldm_x2(uint32_t& b0, uint32_t& b1, uint32_t addr) {
    asm volatile("ldmatrix.sync.aligned.m8n8.x2.shared.b16 {%0,%1}, [%2];"
                 : "=r"(b0), "=r"(b1) : "r"(addr));
}
__device__ __forceinline__ void mma16816(float* d, const uint32_t* a, const uint32_t* b) {
    asm volatile("mma.sync.aligned.m16n8k16.row.col.f32.f16.f16.f32 "
                 "{%0,%1,%2,%3}, {%4,%5,%6,%7}, {%8,%9}, {%0,%1,%2,%3};"
                 : "+f"(d[0]), "+f"(d[1]), "+f"(d[2]), "+f"(d[3])
                 : "r"(a[0]), "r"(a[1]), "r"(a[2]), "r"(a[3]), "r"(b[0]), "r"(b[1]));
}
__device__ __forceinline__ float tanhfast(float x) {
    float y;
    asm("tanh.approx.f32 %0, %1;" : "=f"(y) : "f"(x));
    return y;
}
__device__ __forceinline__ float sigfast(float x) {
    return 0.5f * tanhfast(0.5f * x) + 0.5f;
}
__device__ __forceinline__ __half2 u2h2(uint32_t v) {
    __half2 h;
    *reinterpret_cast<uint32_t*>(&h) = v;
    return h;
}

// ---------------------------------------------------------------------------
// fp16 tensor-core GEMM: out[m][n] = sum_k A[m][k]*W[n][k] + ba[n] + bb[n]
// BM=128, BN=128, BK=32, 256 threads, warp grid 2(m) x 4(n), m16n8k16 HMMA.
// A, W fp32 in gmem, converted to fp16 in smem (padded stride 40 halves).
// ---------------------------------------------------------------------------
template <int N, int K>
__global__ void __launch_bounds__(256) gemm_hmma(const float* __restrict__ A,
                                                 const float* __restrict__ W,
                                                 const float* __restrict__ ba,
                                                 const float* __restrict__ bb,
                                                 float* __restrict__ out)
{
    constexpr int BM = 128, BN = 128, BK = 32;
    constexpr int LDS_ = 40;                 // padded half stride (80B, conflict-free ldmatrix)
    constexpr int KT = (K + BK - 1) / BK;    // k-tiles

    __shared__ alignas(16) __half As[BM * LDS_];
    __shared__ alignas(16) __half Ws[BN * LDS_];

    const int tid  = threadIdx.x;
    const int bm   = blockIdx.y * BM;
    const int bn   = blockIdx.x * BN;
    const int w    = tid >> 5;
    const int lane = tid & 31;
    const int wm   = (w >> 2) * 64;   // warp m offset in tile
    const int wn   = (w & 3) * 32;    // warp n offset in tile

    float acc[4][4][4];
#pragma unroll
    for (int mt = 0; mt < 4; mt++)
#pragma unroll
        for (int nt = 0; nt < 4; nt++)
#pragma unroll
            for (int i = 0; i < 4; i++) acc[mt][nt][i] = 0.f;

    for (int kt = 0; kt < KT; kt++) {
        const int kbase = kt * BK;
        // load A tile: 128 rows x 16 float2, convert to fp16
#pragma unroll
        for (int i = 0; i < 8; i++) {
            int idx = tid + i * 256;          // 0..2047
            int m = idx >> 4, kc = idx & 15;  // kc: float2 index within 32-k tile
            int k = kbase + kc * 2;
            float2 v = make_float2(0.f, 0.f);
            if (k + 1 < K)      v = *(const float2*)(A + (size_t)(bm + m) * K + k);
            else if (k < K)     v.x = A[(size_t)(bm + m) * K + k];
            *(__half2*)&As[m * LDS_ + kc * 2] = __floats2half2_rn(v.x, v.y);
        }
        // load W tile
#pragma unroll
        for (int i = 0; i < 8; i++) {
            int idx = tid + i * 256;
            int n = idx >> 4, kc = idx & 15;
            int k = kbase + kc * 2;
            float2 v = make_float2(0.f, 0.f);
            if (k + 1 < K)      v = *(const float2*)(W + (size_t)(bn + n) * K + k);
            else if (k < K)     v.x = W[(size_t)(bn + n) * K + k];
            *(__half2*)&Ws[n * LDS_ + kc * 2] = __floats2half2_rn(v.x, v.y);
        }
        __syncthreads();

#pragma unroll
        for (int kk = 0; kk < BK; kk += 16) {
            uint32_t af[4][4];
#pragma unroll
            for (int mt = 0; mt < 4; mt++) {
                uint32_t addr = s2u(&As[(wm + mt * 16 + (lane & 15)) * LDS_ + kk + (lane >> 4) * 8]);
                ldm_x4(af[mt][0], af[mt][1], af[mt][2], af[mt][3], addr);
            }
            uint32_t bf[4][2];
#pragma unroll
            for (int nt = 0; nt < 4; nt++) {
                int l = lane & 15;
                uint32_t addr = s2u(&Ws[(wn + nt * 8 + (l & 7)) * LDS_ + kk + ((l >> 3) & 1) * 8]);
                ldm_x2(bf[nt][0], bf[nt][1], addr);
            }
#pragma unroll
            for (int mt = 0; mt < 4; mt++)
#pragma unroll
                for (int nt = 0; nt < 4; nt++)
                    mma16816(acc[mt][nt], af[mt], bf[nt]);
        }
        __syncthreads();
    }

    // epilogue: d0,d1 -> (row lane>>2, col (lane&3)*2); d2,d3 -> row+8
#pragma unroll
    for (int mt = 0; mt < 4; mt++) {
#pragma unroll
        for (int nt = 0; nt < 4; nt++) {
            int row = bm + wm + mt * 16 + (lane >> 2);
            int col = bn + wn + nt * 8 + (lane & 3) * 2;
            float b0 = __ldg(ba + col) + __ldg(bb + col);
            float b1 = __ldg(ba + col + 1) + __ldg(bb + col + 1);
            *(float2*)(out + (size_t)row * N + col) =
                make_float2(acc[mt][nt][0] + b0, acc[mt][nt][1] + b1);
            *(float2*)(out + (size_t)(row + 8) * N + col) =
                make_float2(acc[mt][nt][2] + b0, acc[mt][nt][3] + b1);
        }
    }
}

// ---------------------------------------------------------------------------
// LSTM layer 1: 128 blocks x 512 threads, 8 batch rows/block.
// Phase 1: thread g=tid (gate-unit row of W1_hh) keeps its 128 fp16 weights in
//          64 half2 REGISTERS; HFMA2 over (even-k, odd-k) lanes for 8 rows.
// Phase 2: thread (row=tid>>6, jp=tid&63) does gates->h for 2 hidden units.
// ---------------------------------------------------------------------------
__global__ void __launch_bounds__(512) lstm1_kernel(const float* __restrict__ xw,   // [B][T][512]
                                                    const float* __restrict__ Whh,  // [512][128]
                                                    float* __restrict__ hs1)        // [B][T][128]
{
    __shared__ float   gsum[8][512];        // [row][g]   16KB
    __shared__ __half2 hsh[8][64];          // [row][kp]  2KB  (units 2kp,2kp+1)

    const int tid = threadIdx.x;
    const int b0  = blockIdx.x * 8;

    // weights -> registers (time-invariant)
    __half2 wr[64];
    {
        const float* wp = Whh + (size_t)tid * 128;
#pragma unroll
        for (int i = 0; i < 64; i++) wr[i] = __floats2half2_rn(wp[2 * i], wp[2 * i + 1]);
    }

    const int arow = tid >> 6;   // 0..7
    const int ajp  = tid & 63;   // hidden-unit pair

    for (int i = tid; i < 8 * 64; i += 512) ((__half2*)hsh)[i] = __floats2half2_rn(0.f, 0.f);
    __syncthreads();

    const float* xbase = xw + (size_t)(b0 + arow) * Tc * 512;
    float2 px[4];
#pragma unroll
    for (int gg = 0; gg < 4; gg++)
        px[gg] = *(const float2*)(xbase + gg * 128 + 2 * ajp);

    float c0 = 0.f, c1 = 0.f;

    for (int t = 0; t < Tc; t++) {
        // ---- phase 1: recurrent matvec for 8 batch rows ----
        __half2 acc[8];
#pragma unroll
        for (int r = 0; r < 8; r++) acc[r] = __floats2half2_rn(0.f, 0.f);

#pragma unroll
        for (int kp = 0; kp < 64; kp += 4) {
            __half2 w0 = wr[kp], w1 = wr[kp + 1], w2 = wr[kp + 2], w3 = wr[kp + 3];
#pragma unroll
            for (int r = 0; r < 8; r++) {
                uint4 hv = *(const uint4*)&hsh[r][kp];   // broadcast LDS.128
                acc[r] = __hfma2(w0, u2h2(hv.x), acc[r]);
                acc[r] = __hfma2(w1, u2h2(hv.y), acc[r]);
                acc[r] = __hfma2(w2, u2h2(hv.z), acc[r]);
                acc[r] = __hfma2(w3, u2h2(hv.w), acc[r]);
            }
        }
#pragma unroll
        for (int r = 0; r < 8; r++) {
            float2 p = __half22float2(acc[r]);
            gsum[r][tid] = p.x + p.y;
        }
        __syncthreads();

        // ---- phase 2: activations for (arow, units 2ajp, 2ajp+1) ----
        {
            float2 vi = *(const float2*)&gsum[arow][0 * 128 + 2 * ajp];
            float2 vf = *(const float2*)&gsum[arow][1 * 128 + 2 * ajp];
            float2 vg = *(const float2*)&gsum[arow][2 * 128 + 2 * ajp];
            float2 vo = *(const float2*)&gsum[arow][3 * 128 + 2 * ajp];
            float zi0 = vi.x + px[0].x, zi1 = vi.y + px[0].y;
            float zf0 = vf.x + px[1].x, zf1 = vf.y + px[1].y;
            float zg0 = vg.x + px[2].x, zg1 = vg.y + px[2].y;
            float zo0 = vo.x + px[3].x, zo1 = vo.y + px[3].y;

            c0 = sigfast(zf0) * c0 + sigfast(zi0) * tanhfast(zg0);
            float h0 = sigfast(zo0) * tanhfast(c0);
            c1 = sigfast(zf1) * c1 + sigfast(zi1) * tanhfast(zg1);
            float h1 = sigfast(zo1) * tanhfast(c1);

            hsh[arow][ajp] = __floats2half2_rn(h0, h1);
            *(float2*)(hs1 + ((size_t)(b0 + arow) * Tc + t) * 128 + 2 * ajp) =
                make_float2(h0, h1);

            if (t + 1 < Tc) {
                const float* xr = xbase + (size_t)(t + 1) * 512;
#pragma unroll
                for (int gg = 0; gg < 4; gg++)
                    px[gg] = *(const float2*)(xr + gg * 128 + 2 * ajp);
            }
        }
        __syncthreads();
    }
}

// ---------------------------------------------------------------------------
// LSTM layer 2 + FC head: 128 blocks x 512 threads, 8 rows/block.
// Phase 1: thread (g=tid&255, rh=tid>>8) -> rows rh*4..rh*4+3; 32 half2 w regs.
// Phase 2: threads 0..255: (row=tid>>5, jp=tid&31), 2 units each.
// ---------------------------------------------------------------------------
__global__ void __launch_bounds__(512) lstm2_kernel(const float* __restrict__ xw,   // [B][T][256]
                                                    const float* __restrict__ Whh,  // [256][64]
                                                    const float* __restrict__ fc1w,
                                                    const float* __restrict__ fc1b,
                                                    const float* __restrict__ fc2w,
                                                    const float* __restrict__ fc2b,
                                                    float* __restrict__ out)
{
    __shared__ float   gsum[8][256];        // [row][g]  8KB
    __shared__ __half2 hsh[8][32];          // [row][kp] 1KB
    __shared__ float   hfin[8][64];         // final h_n fp32, 2KB

    const int tid = threadIdx.x;
    const int b0  = blockIdx.x * 8;
    const int g   = tid & 255;
    const int rh  = tid >> 8;               // 0/1 -> rows rh*4..rh*4+3

    __half2 wr[32];
    {
        const float* wp = Whh + (size_t)g * 64;
#pragma unroll
        for (int i = 0; i < 32; i++) wr[i] = __floats2half2_rn(wp[2 * i], wp[2 * i + 1]);
    }

    const int arow = tid >> 5;   // 0..7 (valid for tid<256)
    const int ajp  = tid & 31;

    for (int i = tid; i < 8 * 32; i += 512) ((__half2*)hsh)[i] = __floats2half2_rn(0.f, 0.f);
    __syncthreads();

    const float* xbase = xw + (size_t)(b0 + arow) * Tc * 256;
    float2 px[4];
    if (tid < 256) {
#pragma unroll
        for (int gg = 0; gg < 4; gg++)
            px[gg] = *(const float2*)(xbase + gg * 64 + 2 * ajp);
    }

    float c0 = 0.f, c1 = 0.f;

    for (int t = 0; t < Tc; t++) {
        __half2 acc[4];
#pragma unroll
        for (int r = 0; r < 4; r++) acc[r] = __floats2half2_rn(0.f, 0.f);

#pragma unroll
        for (int kp = 0; kp < 32; kp += 4) {
            __half2 w0 = wr[kp], w1 = wr[kp + 1], w2 = wr[kp + 2], w3 = wr[kp + 3];
#pragma unroll
            for (int r = 0; r < 4; r++) {
                uint4 hv = *(const uint4*)&hsh[rh * 4 + r][kp];
                acc[r] = __hfma2(w0, u2h2(hv.x), acc[r]);
                acc[r] = __hfma2(w1, u2h2(hv.y), acc[r]);
                acc[r] = __hfma2(w2, u2h2(hv.z), acc[r]);
                acc[r] = __hfma2(w3, u2h2(hv.w), acc[r]);
            }
        }
#pragma unroll
        for (int r = 0; r < 4; r++) {
            float2 p = __half22float2(acc[r]);
            gsum[rh * 4 + r][g] = p.x + p.y;
        }
        __syncthreads();

        if (tid < 256) {
            float2 vi = *(const float2*)&gsum[arow][0 * 64 + 2 * ajp];
            float2 vf = *(const float2*)&gsum[arow][1 * 64 + 2 * ajp];
            float2 vg = *(const float2*)&gsum[arow][2 * 64 + 2 * ajp];
            float2 vo = *(const float2*)&gsum[arow][3 * 64 + 2 * ajp];
            float zi0 = vi.x + px[0].x, zi1 = vi.y + px[0].y;
            float zf0 = vf.x + px[1].x, zf1 = vf.y + px[1].y;
            float zg0 = vg.x + px[2].x, zg1 = vg.y + px[2].y;
            float zo0 = vo.x + px[3].x, zo1 = vo.y + px[3].y;

            c0 = sigfast(zf0) * c0 + sigfast(zi0) * tanhfast(zg0);
            float h0 = sigfast(zo0) * tanhfast(c0);
            c1 = sigfast(zf1) * c1 + sigfast(zi1) * tanhfast(zg1);
            float h1 = sigfast(zo1) * tanhfast(c1);

            hsh[arow][ajp] = __floats2half2_rn(h0, h1);
            if (t == Tc - 1) {
                hfin[arow][2 * ajp]     = h0;
                hfin[arow][2 * ajp + 1] = h1;
            }
            if (t + 1 < Tc) {
                const float* xr = xbase + (size_t)(t + 1) * 256;
#pragma unroll
                for (int gg = 0; gg < 4; gg++)
                    px[gg] = *(const float2*)(xr + gg * 64 + 2 * ajp);
            }
        }
        __syncthreads();
    }

    // FC head: warp w -> batch row w (warps 0..7), lane = fc1 unit
    const int warp = tid >> 5, lane = tid & 31;
    if (warp < 8) {
        float a = __ldg(fc1b + lane);
#pragma unroll
        for (int k = 0; k < 64; k++)
            a = fmaf(hfin[warp][k], __ldg(fc1w + lane * 64 + k), a);
        a = fmaxf(a, 0.f);
        float v = a * __ldg(fc2w + lane);
#pragma unroll
        for (int off = 16; off; off >>= 1) v += __shfl_down_sync(0xffffffffu, v, off);
        if (lane == 0) out[b0 + warp] = 1.f / (1.f + __expf(-(v + __ldg(fc2b))));
    }
}

// ---------------------------------------------------------------------------
extern "C" void kernel_launch(void* const* d_in, const int* in_sizes, int n_in,
                              void* d_out, int out_size)
{
    (void)in_sizes; (void)n_in; (void)out_size;
    const float* X     = (const float*)d_in[0];
    const float* W1_ih = (const float*)d_in[1];
    const float* W1_hh = (const float*)d_in[2];
    const float* b1_ih = (const float*)d_in[3];
    const float* b1_hh = (const float*)d_in[4];
    const float* W2_ih = (const float*)d_in[5];
    const float* W2_hh = (const float*)d_in[6];
    const float* b2_ih = (const float*)d_in[7];
    const float* b2_hh = (const float*)d_in[8];
    const float* fc1w  = (const float*)d_in[9];
    const float* fc1b  = (const float*)d_in[10];
    const float* fc2w  = (const float*)d_in[11];
    const float* fc2b  = (const float*)d_in[12];
    float* out = (float*)d_out;

    float *xw1, *hs1, *xw2;
    cudaGetSymbolAddress((void**)&xw1, g_xw1);
    cudaGetSymbolAddress((void**)&hs1, g_hs1);
    cudaGetSymbolAddress((void**)&xw2, g_xw2);

    // 1) xw1 = X @ W1_ih^T + b   (tensor-core fp16)
    gemm_hmma<G1c, EMBc><<<dim3(G1c / 128, Mtot / 128), 256>>>(X, W1_ih, b1_ih, b1_hh, xw1);
    // 2) layer-1 recurrence
    lstm1_kernel<<<Bc / 8, 512>>>(xw1, W1_hh, hs1);
    // 3) xw2 = hs1 @ W2_ih^T + b
    gemm_hmma<G2c, H1c><<<dim3(G2c / 128, Mtot / 128), 256>>>(hs1, W2_ih, b2_ih, b2_hh, xw2);
    // 4) layer-2 recurrence + FC head
    lstm2_kernel<<<Bc / 8, 512>>>(xw2, W2_hh, fc1w, fc1b, fc2w, fc2b, out);
}